// round 9
// baseline (speedup 1.0000x reference)
#include <cuda_runtime.h>
#include <math.h>
#include <stdint.h>

#define BB 2
#define SS 2048
#define DD 1024
#define HH 16
#define HD 64
#define NTOK (BB * SS)

// Scratch (allocation-free rule: __device__ globals)
__device__ float g_Q[NTOK * DD];
__device__ float g_K[NTOK * DD];
__device__ float g_V[NTOK * DD];
__device__ float g_A[NTOK * DD];

__device__ __forceinline__ uint32_t f2tf32(float f) {
    uint32_t u;
    asm("cvt.rna.tf32.f32 %0, %1;" : "=r"(u) : "f"(f));
    return u;
}

// ---------------------------------------------------------------------------
// tf32 tensor-core GEMM:  C[M,N] = A[M,K] @ W[N,K]^T + bias[N]
// BM=128, BN=128, BK=32. 256 threads = 8 warps (4m x 2n), warp tile 32x64.
// mma.sync.aligned.m16n8k8.row.col.f32.tf32.tf32.f32
// ---------------------------------------------------------------------------
#define GBM 128
#define GBN 128
#define GBK 32

__global__ __launch_bounds__(256, 2) void gemm_tf32(
    const float* __restrict__ A, const float* __restrict__ W,
    const float* __restrict__ bias, float* __restrict__ C,
    int M, int N, int K)
{
    __shared__ float As[GBM][GBK + 4];
    __shared__ float Bs[GBN][GBK + 4];

    const int tid  = threadIdx.x;
    const int lane = tid & 31;
    const int warp = tid >> 5;
    const int g    = lane >> 2;   // groupID 0..7
    const int tg   = lane & 3;    // threadID_in_group 0..3
    const int wm   = warp >> 1;   // 0..3
    const int wn   = warp & 1;    // 0..1
    const int warpRow = wm * 32;
    const int warpCol = wn * 64;

    const int bm = blockIdx.y * GBM;
    const int bn = blockIdx.x * GBN;

    float acc[2][8][4];
#pragma unroll
    for (int i = 0; i < 2; i++)
#pragma unroll
        for (int j = 0; j < 8; j++)
#pragma unroll
            for (int r = 0; r < 4; r++) acc[i][j][r] = 0.f;

    const int f  = tid & 7;     // float4 col within 32-wide k slab
    const int r0 = tid >> 3;    // 0..31

    const float* Ag = A + (size_t)(bm + r0) * K + f * 4;
    const float* Wg = W + (size_t)(bn + r0) * K + f * 4;

    for (int k0 = 0; k0 < K; k0 += GBK) {
        __syncthreads();
#pragma unroll
        for (int i = 0; i < 4; i++) {
            float4 av = *(const float4*)(Ag + (size_t)(i * 32) * K + k0);
            float4 wv = *(const float4*)(Wg + (size_t)(i * 32) * K + k0);
            int rr = r0 + i * 32;
            As[rr][f * 4 + 0] = __uint_as_float(f2tf32(av.x));
            As[rr][f * 4 + 1] = __uint_as_float(f2tf32(av.y));
            As[rr][f * 4 + 2] = __uint_as_float(f2tf32(av.z));
            As[rr][f * 4 + 3] = __uint_as_float(f2tf32(av.w));
            Bs[rr][f * 4 + 0] = __uint_as_float(f2tf32(wv.x));
            Bs[rr][f * 4 + 1] = __uint_as_float(f2tf32(wv.y));
            Bs[rr][f * 4 + 2] = __uint_as_float(f2tf32(wv.z));
            Bs[rr][f * 4 + 3] = __uint_as_float(f2tf32(wv.w));
        }
        __syncthreads();

#pragma unroll
        for (int kk = 0; kk < 4; kk++) {
            const int kb = kk * 8;
            uint32_t a[2][4];
#pragma unroll
            for (int mf = 0; mf < 2; mf++) {
                const int r = warpRow + mf * 16 + g;
                a[mf][0] = __float_as_uint(As[r][kb + tg]);
                a[mf][1] = __float_as_uint(As[r + 8][kb + tg]);
                a[mf][2] = __float_as_uint(As[r][kb + tg + 4]);
                a[mf][3] = __float_as_uint(As[r + 8][kb + tg + 4]);
            }
            uint32_t b[8][2];
#pragma unroll
            for (int nf = 0; nf < 8; nf++) {
                const int c = warpCol + nf * 8 + g;
                b[nf][0] = __float_as_uint(Bs[c][kb + tg]);
                b[nf][1] = __float_as_uint(Bs[c][kb + tg + 4]);
            }
#pragma unroll
            for (int mf = 0; mf < 2; mf++)
#pragma unroll
                for (int nf = 0; nf < 8; nf++) {
                    asm volatile(
                        "mma.sync.aligned.m16n8k8.row.col.f32.tf32.tf32.f32 "
                        "{%0,%1,%2,%3}, {%4,%5,%6,%7}, {%8,%9}, {%0,%1,%2,%3};"
                        : "+f"(acc[mf][nf][0]), "+f"(acc[mf][nf][1]),
                          "+f"(acc[mf][nf][2]), "+f"(acc[mf][nf][3])
                        : "r"(a[mf][0]), "r"(a[mf][1]), "r"(a[mf][2]), "r"(a[mf][3]),
                          "r"(b[nf][0]), "r"(b[nf][1]));
                }
        }
    }

#pragma unroll
    for (int mf = 0; mf < 2; mf++) {
        const int r = bm + warpRow + mf * 16 + g;
#pragma unroll
        for (int nf = 0; nf < 8; nf++) {
            const int c = bn + warpCol + nf * 8 + 2 * tg;
            float2 bv = *(const float2*)&bias[c];
            float2 o0 = make_float2(acc[mf][nf][0] + bv.x, acc[mf][nf][1] + bv.y);
            float2 o1 = make_float2(acc[mf][nf][2] + bv.x, acc[mf][nf][3] + bv.y);
            *(float2*)&C[(size_t)r * N + c] = o0;
            *(float2*)&C[(size_t)(r + 8) * N + c] = o1;
        }
    }
}

// ---------------------------------------------------------------------------
// Causal ALiBi flash attention, v2.
// Block = 128 threads = 64 query rows x 2 half-threads. Each block processes
// TWO q-tiles (p and 31-p) so per-block work is constant (33 key-tiles).
// K/V tile in smem with +4-float offset between halves (bank-conflict-free).
// ---------------------------------------------------------------------------
#define KSTRIDE 72   // 32 | pad4 | 32 | pad4

__device__ __forceinline__ void attn_tile(
    int qt, int h, int b,
    const float* __restrict__ Q, const float* __restrict__ Kg,
    const float* __restrict__ Vg, float* __restrict__ O,
    float (*Ks)[KSTRIDE], float (*Vs)[KSTRIDE])
{
    const int t    = threadIdx.x;
    const int row  = t >> 1;
    const int half = t & 1;
    const int qrow = qt * 64 + row;
    const size_t base = ((size_t)b * SS) * DD + (size_t)h * HD;

    float q[32];
    {
        const float* qp = Q + base + (size_t)qrow * DD + half * 32;
#pragma unroll
        for (int d = 0; d < 32; d += 4) *(float4*)&q[d] = *(const float4*)(qp + d);
    }
    float o[32];
#pragma unroll
    for (int d = 0; d < 32; d++) o[d] = 0.f;

    float m = -1e30f, l = 0.f;
    const float slope = exp2f(-0.5f * (float)(h + 1));
    const float scale = 0.125f;
    const int hoff = half * 36;

    for (int kt = 0; kt <= qt; kt++) {
        __syncthreads();
        const float* kb = Kg + base + (size_t)(kt * 64) * DD;
        const float* vb = Vg + base + (size_t)(kt * 64) * DD;
#pragma unroll
        for (int i = 0; i < 8; i++) {
            int n = i * 128 + t;              // float4 index in 64x16 grid
            int r = n >> 4, c = (n & 15) << 2;
            int cs = c + (c >= 32 ? 4 : 0);   // padded dest col
            *(float4*)&Ks[r][cs] = *(const float4*)(kb + (size_t)r * DD + c);
            *(float4*)&Vs[r][cs] = *(const float4*)(vb + (size_t)r * DD + c);
        }
        __syncthreads();

        const bool diag = (kt == qt);

#pragma unroll 1
        for (int j0 = 0; j0 < 64; j0 += 16) {
            float s[16];
            float tmax = -1e30f;
#pragma unroll
            for (int jj = 0; jj < 16; jj++) {
                const int j = j0 + jj;
                const float* kr = &Ks[j][hoff];
                float a0 = 0.f, a1 = 0.f, a2 = 0.f, a3 = 0.f;
#pragma unroll
                for (int d = 0; d < 32; d += 4) {
                    float4 kv = *(const float4*)(kr + d);
                    a0 += q[d + 0] * kv.x;
                    a1 += q[d + 1] * kv.y;
                    a2 += q[d + 2] * kv.z;
                    a3 += q[d + 3] * kv.w;
                }
                float part = (a0 + a1) + (a2 + a3);
                part += __shfl_xor_sync(0xffffffffu, part, 1);
                const int kpos = kt * 64 + j;
                float sc = part * scale + slope * (float)(kpos - qrow);
                if (diag && kpos > qrow) sc = -1e30f;
                s[jj] = sc;
                tmax = fmaxf(tmax, sc);
            }
            const float mnew = fmaxf(m, tmax);
            const float alpha = __expf(m - mnew);
            float psum = 0.f;
#pragma unroll
            for (int jj = 0; jj < 16; jj++) {
                s[jj] = __expf(s[jj] - mnew);
                psum += s[jj];
            }
            l = l * alpha + psum;
            m = mnew;
#pragma unroll
            for (int d = 0; d < 32; d++) o[d] *= alpha;
#pragma unroll
            for (int jj = 0; jj < 16; jj++) {
                const float p = s[jj];
                const float* vr = &Vs[j0 + jj][hoff];
#pragma unroll
                for (int d = 0; d < 32; d += 4) {
                    float4 vv = *(const float4*)(vr + d);
                    o[d + 0] += p * vv.x;
                    o[d + 1] += p * vv.y;
                    o[d + 2] += p * vv.z;
                    o[d + 3] += p * vv.w;
                }
            }
        }
    }

    const float inv = 1.f / l;
    float* op = O + base + (size_t)qrow * DD + half * 32;
#pragma unroll
    for (int d = 0; d < 32; d += 4) {
        float4 ov = make_float4(o[d] * inv, o[d + 1] * inv,
                                o[d + 2] * inv, o[d + 3] * inv);
        *(float4*)(op + d) = ov;
    }
}

__global__ __launch_bounds__(128, 4) void attn_kernel2(
    const float* __restrict__ Q, const float* __restrict__ K,
    const float* __restrict__ V, float* __restrict__ O)
{
    __shared__ float Ks[64][KSTRIDE];
    __shared__ float Vs[64][KSTRIDE];
    const int p = blockIdx.x;   // 0..15
    const int h = blockIdx.y;
    const int b = blockIdx.z;
    attn_tile(p,      h, b, Q, K, V, O, Ks, Vs);
    attn_tile(31 - p, h, b, Q, K, V, O, Ks, Vs);
}

// ---------------------------------------------------------------------------
extern "C" void kernel_launch(void* const* d_in, const int* in_sizes, int n_in,
                              void* d_out, int out_size)
{
    (void)in_sizes; (void)n_in; (void)out_size;
    const float* x   = (const float*)d_in[0];
    const float* q_w = (const float*)d_in[1];
    const float* q_b = (const float*)d_in[2];
    const float* k_w = (const float*)d_in[3];
    const float* k_b = (const float*)d_in[4];
    const float* v_w = (const float*)d_in[5];
    const float* v_b = (const float*)d_in[6];
    const float* o_w = (const float*)d_in[7];
    const float* o_b = (const float*)d_in[8];
    float* out = (float*)d_out;

    float *Qp, *Kp, *Vp, *Ap;
    cudaGetSymbolAddress((void**)&Qp, g_Q);
    cudaGetSymbolAddress((void**)&Kp, g_K);
    cudaGetSymbolAddress((void**)&Vp, g_V);
    cudaGetSymbolAddress((void**)&Ap, g_A);

    dim3 gg(DD / GBN, NTOK / GBM);   // (8, 32)
    gemm_tf32<<<gg, 256>>>(x, q_w, q_b, Qp, NTOK, DD, DD);
    gemm_tf32<<<gg, 256>>>(x, k_w, k_b, Kp, NTOK, DD, DD);
    gemm_tf32<<<gg, 256>>>(x, v_w, v_b, Vp, NTOK, DD, DD);

    dim3 ga(SS / 128, HH, BB);       // (16, 16, 2)
    attn_kernel2<<<ga, 128>>>(Qp, Kp, Vp, Ap);

    gemm_tf32<<<gg, 256>>>(Ap, o_w, o_b, out, NTOK, DD, DD);
}

// round 10
// speedup vs baseline: 1.0082x; 1.0082x over previous
#include <cuda_runtime.h>
#include <math.h>
#include <stdint.h>

#define BB 2
#define SS 2048
#define DD 1024
#define HH 16
#define HD 64
#define NTOK (BB * SS)

// Scratch (allocation-free rule: __device__ globals)
__device__ float g_Q[NTOK * DD];
__device__ float g_K[NTOK * DD];
__device__ float g_V[NTOK * DD];
__device__ float g_A[NTOK * DD];

__device__ __forceinline__ uint32_t f2tf32(float f) {
    uint32_t u;
    asm("cvt.rna.tf32.f32 %0, %1;" : "=r"(u) : "f"(f));
    return u;
}

// ---------------------------------------------------------------------------
// tf32 tensor-core GEMM:  C[M,N] = A[M,K] @ W[N,K]^T + bias[N]
// BM=128, BN=128, BK=32. 256 threads = 8 warps (4m x 2n), warp tile 32x64.
// mma.sync.aligned.m16n8k8.row.col.f32.tf32.tf32.f32
// ---------------------------------------------------------------------------
#define GBM 128
#define GBN 128
#define GBK 32

__global__ __launch_bounds__(256, 2) void gemm_tf32(
    const float* __restrict__ A, const float* __restrict__ W,
    const float* __restrict__ bias, float* __restrict__ C,
    int M, int N, int K)
{
    __shared__ float As[GBM][GBK + 4];
    __shared__ float Bs[GBN][GBK + 4];

    const int tid  = threadIdx.x;
    const int lane = tid & 31;
    const int warp = tid >> 5;
    const int g    = lane >> 2;   // groupID 0..7
    const int tg   = lane & 3;    // threadID_in_group 0..3
    const int wm   = warp >> 1;   // 0..3
    const int wn   = warp & 1;    // 0..1
    const int warpRow = wm * 32;
    const int warpCol = wn * 64;

    const int bm = blockIdx.y * GBM;
    const int bn = blockIdx.x * GBN;

    float acc[2][8][4];
#pragma unroll
    for (int i = 0; i < 2; i++)
#pragma unroll
        for (int j = 0; j < 8; j++)
#pragma unroll
            for (int r = 0; r < 4; r++) acc[i][j][r] = 0.f;

    const int f  = tid & 7;     // float4 col within 32-wide k slab
    const int r0 = tid >> 3;    // 0..31

    const float* Ag = A + (size_t)(bm + r0) * K + f * 4;
    const float* Wg = W + (size_t)(bn + r0) * K + f * 4;

    for (int k0 = 0; k0 < K; k0 += GBK) {
        __syncthreads();
#pragma unroll
        for (int i = 0; i < 4; i++) {
            float4 av = *(const float4*)(Ag + (size_t)(i * 32) * K + k0);
            float4 wv = *(const float4*)(Wg + (size_t)(i * 32) * K + k0);
            int rr = r0 + i * 32;
            As[rr][f * 4 + 0] = __uint_as_float(f2tf32(av.x));
            As[rr][f * 4 + 1] = __uint_as_float(f2tf32(av.y));
            As[rr][f * 4 + 2] = __uint_as_float(f2tf32(av.z));
            As[rr][f * 4 + 3] = __uint_as_float(f2tf32(av.w));
            Bs[rr][f * 4 + 0] = __uint_as_float(f2tf32(wv.x));
            Bs[rr][f * 4 + 1] = __uint_as_float(f2tf32(wv.y));
            Bs[rr][f * 4 + 2] = __uint_as_float(f2tf32(wv.z));
            Bs[rr][f * 4 + 3] = __uint_as_float(f2tf32(wv.w));
        }
        __syncthreads();

#pragma unroll
        for (int kk = 0; kk < 4; kk++) {
            const int kb = kk * 8;
            uint32_t a[2][4];
#pragma unroll
            for (int mf = 0; mf < 2; mf++) {
                const int r = warpRow + mf * 16 + g;
                a[mf][0] = __float_as_uint(As[r][kb + tg]);
                a[mf][1] = __float_as_uint(As[r + 8][kb + tg]);
                a[mf][2] = __float_as_uint(As[r][kb + tg + 4]);
                a[mf][3] = __float_as_uint(As[r + 8][kb + tg + 4]);
            }
            uint32_t b[8][2];
#pragma unroll
            for (int nf = 0; nf < 8; nf++) {
                const int c = warpCol + nf * 8 + g;
                b[nf][0] = __float_as_uint(Bs[c][kb + tg]);
                b[nf][1] = __float_as_uint(Bs[c][kb + tg + 4]);
            }
#pragma unroll
            for (int mf = 0; mf < 2; mf++)
#pragma unroll
                for (int nf = 0; nf < 8; nf++) {
                    asm volatile(
                        "mma.sync.aligned.m16n8k8.row.col.f32.tf32.tf32.f32 "
                        "{%0,%1,%2,%3}, {%4,%5,%6,%7}, {%8,%9}, {%0,%1,%2,%3};"
                        : "+f"(acc[mf][nf][0]), "+f"(acc[mf][nf][1]),
                          "+f"(acc[mf][nf][2]), "+f"(acc[mf][nf][3])
                        : "r"(a[mf][0]), "r"(a[mf][1]), "r"(a[mf][2]), "r"(a[mf][3]),
                          "r"(b[nf][0]), "r"(b[nf][1]));
                }
        }
    }

#pragma unroll
    for (int mf = 0; mf < 2; mf++) {
        const int r = bm + warpRow + mf * 16 + g;
#pragma unroll
        for (int nf = 0; nf < 8; nf++) {
            const int c = bn + warpCol + nf * 8 + 2 * tg;
            float2 bv = *(const float2*)&bias[c];
            float2 o0 = make_float2(acc[mf][nf][0] + bv.x, acc[mf][nf][1] + bv.y);
            float2 o1 = make_float2(acc[mf][nf][2] + bv.x, acc[mf][nf][3] + bv.y);
            *(float2*)&C[(size_t)r * N + c] = o0;
            *(float2*)&C[(size_t)(r + 8) * N + c] = o1;
        }
    }
}

// ---------------------------------------------------------------------------
// Causal ALiBi flash attention, v2.
// Block = 128 threads = 64 query rows x 2 half-threads. Each block processes
// TWO q-tiles (p and 31-p) so per-block work is constant (33 key-tiles).
// K/V tile in smem with +4-float offset between halves (bank-conflict-free).
// ---------------------------------------------------------------------------
#define KSTRIDE 72   // 32 | pad4 | 32 | pad4

__device__ __forceinline__ void attn_tile(
    int qt, int h, int b,
    const float* __restrict__ Q, const float* __restrict__ Kg,
    const float* __restrict__ Vg, float* __restrict__ O,
    float (*Ks)[KSTRIDE], float (*Vs)[KSTRIDE])
{
    const int t    = threadIdx.x;
    const int row  = t >> 1;
    const int half = t & 1;
    const int qrow = qt * 64 + row;
    const size_t base = ((size_t)b * SS) * DD + (size_t)h * HD;

    float q[32];
    {
        const float* qp = Q + base + (size_t)qrow * DD + half * 32;
#pragma unroll
        for (int d = 0; d < 32; d += 4) *(float4*)&q[d] = *(const float4*)(qp + d);
    }
    float o[32];
#pragma unroll
    for (int d = 0; d < 32; d++) o[d] = 0.f;

    float m = -1e30f, l = 0.f;
    const float slope = exp2f(-0.5f * (float)(h + 1));
    const float scale = 0.125f;
    const int hoff = half * 36;

    for (int kt = 0; kt <= qt; kt++) {
        __syncthreads();
        const float* kb = Kg + base + (size_t)(kt * 64) * DD;
        const float* vb = Vg + base + (size_t)(kt * 64) * DD;
#pragma unroll
        for (int i = 0; i < 8; i++) {
            int n = i * 128 + t;              // float4 index in 64x16 grid
            int r = n >> 4, c = (n & 15) << 2;
            int cs = c + (c >= 32 ? 4 : 0);   // padded dest col
            *(float4*)&Ks[r][cs] = *(const float4*)(kb + (size_t)r * DD + c);
            *(float4*)&Vs[r][cs] = *(const float4*)(vb + (size_t)r * DD + c);
        }
        __syncthreads();

        const bool diag = (kt == qt);

#pragma unroll 1
        for (int j0 = 0; j0 < 64; j0 += 16) {
            float s[16];
            float tmax = -1e30f;
#pragma unroll
            for (int jj = 0; jj < 16; jj++) {
                const int j = j0 + jj;
                const float* kr = &Ks[j][hoff];
                float a0 = 0.f, a1 = 0.f, a2 = 0.f, a3 = 0.f;
#pragma unroll
                for (int d = 0; d < 32; d += 4) {
                    float4 kv = *(const float4*)(kr + d);
                    a0 += q[d + 0] * kv.x;
                    a1 += q[d + 1] * kv.y;
                    a2 += q[d + 2] * kv.z;
                    a3 += q[d + 3] * kv.w;
                }
                float part = (a0 + a1) + (a2 + a3);
                part += __shfl_xor_sync(0xffffffffu, part, 1);
                const int kpos = kt * 64 + j;
                float sc = part * scale + slope * (float)(kpos - qrow);
                if (diag && kpos > qrow) sc = -1e30f;
                s[jj] = sc;
                tmax = fmaxf(tmax, sc);
            }
            const float mnew = fmaxf(m, tmax);
            const float alpha = __expf(m - mnew);
            float psum = 0.f;
#pragma unroll
            for (int jj = 0; jj < 16; jj++) {
                s[jj] = __expf(s[jj] - mnew);
                psum += s[jj];
            }
            l = l * alpha + psum;
            m = mnew;
#pragma unroll
            for (int d = 0; d < 32; d++) o[d] *= alpha;
#pragma unroll
            for (int jj = 0; jj < 16; jj++) {
                const float p = s[jj];
                const float* vr = &Vs[j0 + jj][hoff];
#pragma unroll
                for (int d = 0; d < 32; d += 4) {
                    float4 vv = *(const float4*)(vr + d);
                    o[d + 0] += p * vv.x;
                    o[d + 1] += p * vv.y;
                    o[d + 2] += p * vv.z;
                    o[d + 3] += p * vv.w;
                }
            }
        }
    }

    const float inv = 1.f / l;
    float* op = O + base + (size_t)qrow * DD + half * 32;
#pragma unroll
    for (int d = 0; d < 32; d += 4) {
        float4 ov = make_float4(o[d] * inv, o[d + 1] * inv,
                                o[d + 2] * inv, o[d + 3] * inv);
        *(float4*)(op + d) = ov;
    }
}

__global__ __launch_bounds__(128, 4) void attn_kernel2(
    const float* __restrict__ Q, const float* __restrict__ K,
    const float* __restrict__ V, float* __restrict__ O)
{
    __shared__ float Ks[64][KSTRIDE];
    __shared__ float Vs[64][KSTRIDE];
    const int p = blockIdx.x;   // 0..15
    const int h = blockIdx.y;
    const int b = blockIdx.z;
    attn_tile(p,      h, b, Q, K, V, O, Ks, Vs);
    attn_tile(31 - p, h, b, Q, K, V, O, Ks, Vs);
}

// ---------------------------------------------------------------------------
extern "C" void kernel_launch(void* const* d_in, const int* in_sizes, int n_in,
                              void* d_out, int out_size)
{
    (void)in_sizes; (void)n_in; (void)out_size;
    const float* x   = (const float*)d_in[0];
    const float* q_w = (const float*)d_in[1];
    const float* q_b = (const float*)d_in[2];
    const float* k_w = (const float*)d_in[3];
    const float* k_b = (const float*)d_in[4];
    const float* v_w = (const float*)d_in[5];
    const float* v_b = (const float*)d_in[6];
    const float* o_w = (const float*)d_in[7];
    const float* o_b = (const float*)d_in[8];
    float* out = (float*)d_out;

    float *Qp, *Kp, *Vp, *Ap;
    cudaGetSymbolAddress((void**)&Qp, g_Q);
    cudaGetSymbolAddress((void**)&Kp, g_K);
    cudaGetSymbolAddress((void**)&Vp, g_V);
    cudaGetSymbolAddress((void**)&Ap, g_A);

    dim3 gg(DD / GBN, NTOK / GBM);   // (8, 32)
    gemm_tf32<<<gg, 256>>>(x, q_w, q_b, Qp, NTOK, DD, DD);
    gemm_tf32<<<gg, 256>>>(x, k_w, k_b, Kp, NTOK, DD, DD);
    gemm_tf32<<<gg, 256>>>(x, v_w, v_b, Vp, NTOK, DD, DD);

    dim3 ga(SS / 128, HH, BB);       // (16, 16, 2)
    attn_kernel2<<<ga, 128>>>(Qp, Kp, Vp, Ap);

    gemm_tf32<<<gg, 256>>>(Ap, o_w, o_b, out, NTOK, DD, DD);
}